// round 6
// baseline (speedup 1.0000x reference)
#include <cuda_runtime.h>

// Problem constants
#define Bsz   32
#define Tlen  512
#define Dm    1024
#define Hn    16
#define HDm   64
#define Mrows (Bsz * Tlen)   // 16384

// Scratch: __device__ globals (no cudaMalloc allowed). 5 x 64MB.
__device__ __align__(128) float g_h[(size_t)Mrows * Dm];
__device__ __align__(128) float g_k[(size_t)Mrows * Dm];   // [B,H,T,HD]
__device__ __align__(128) float g_q[(size_t)Mrows * Dm];   // [B,H,T,HD]
__device__ __align__(128) float g_v[(size_t)Mrows * Dm];   // [B,H,T,HD]
__device__ __align__(128) float g_attn[(size_t)Mrows * Dm]; // [B,T,H,HD] = [M,D]

// ---------------------------------------------------------------------------
// SGEMM: C[M,N] = A[M,K] @ B[K,N] + bias[N]   (all row-major, fp32)
// 128x128 block tile, BK=8, 256 threads, 8x8 per thread (2x2 of 4x4 quads).
// ---------------------------------------------------------------------------
__global__ __launch_bounds__(256, 2)
void sgemm_bias(const float* __restrict__ A, const float* __restrict__ B,
                const float* __restrict__ bias, float* __restrict__ C,
                int M, int N, int K)
{
    __shared__ float As[8][128];
    __shared__ float Bs[8][128];

    const int tid = threadIdx.x;
    const int m0 = blockIdx.y * 128;
    const int n0 = blockIdx.x * 128;

    const int aRow = tid >> 1;             // 0..127
    const int aCol = (tid & 1) << 2;       // 0 or 4
    const int bRow = tid >> 5;             // 0..7
    const int bCol = (tid & 31) << 2;      // 0..124

    const int tx = tid & 15, ty = tid >> 4;

    float acc[8][8];
#pragma unroll
    for (int i = 0; i < 8; i++)
#pragma unroll
        for (int j = 0; j < 8; j++) acc[i][j] = 0.f;

    const float* Aptr = A + (size_t)(m0 + aRow) * K + aCol;
    const float* Bptr = B + (size_t)bRow * N + n0 + bCol;

    for (int k0 = 0; k0 < K; k0 += 8) {
        float4 av = *(const float4*)(Aptr + k0);
        As[aCol + 0][aRow] = av.x;
        As[aCol + 1][aRow] = av.y;
        As[aCol + 2][aRow] = av.z;
        As[aCol + 3][aRow] = av.w;
        *(float4*)&Bs[bRow][bCol] = *(const float4*)(Bptr + (size_t)k0 * N);
        __syncthreads();

#pragma unroll
        for (int kk = 0; kk < 8; kk++) {
            float a[8], b[8];
            *(float4*)(a)     = *(const float4*)&As[kk][ty * 4];
            *(float4*)(a + 4) = *(const float4*)&As[kk][64 + ty * 4];
            *(float4*)(b)     = *(const float4*)&Bs[kk][tx * 4];
            *(float4*)(b + 4) = *(const float4*)&Bs[kk][64 + tx * 4];
#pragma unroll
            for (int i = 0; i < 8; i++)
#pragma unroll
                for (int j = 0; j < 8; j++)
                    acc[i][j] = fmaf(a[i], b[j], acc[i][j]);
        }
        __syncthreads();
    }

    float bsv[8];
    *(float4*)(bsv)     = *(const float4*)&bias[n0 + tx * 4];
    *(float4*)(bsv + 4) = *(const float4*)&bias[n0 + 64 + tx * 4];

#pragma unroll
    for (int i = 0; i < 8; i++) {
        const int m = m0 + ((i < 4) ? (ty * 4 + i) : (60 + ty * 4 + i));
        float4 v0, v1;
        v0.x = acc[i][0] + bsv[0]; v0.y = acc[i][1] + bsv[1];
        v0.z = acc[i][2] + bsv[2]; v0.w = acc[i][3] + bsv[3];
        v1.x = acc[i][4] + bsv[4]; v1.y = acc[i][5] + bsv[5];
        v1.z = acc[i][6] + bsv[6]; v1.w = acc[i][7] + bsv[7];
        *(float4*)&C[(size_t)m * N + n0 + tx * 4]      = v0;
        *(float4*)&C[(size_t)m * N + n0 + 64 + tx * 4] = v1;
    }
}

// ---------------------------------------------------------------------------
// QKV projection GEMM:
//   C[b,h,t,e] = sum_d A[(b,t),d] * W[h,d,e] + bias[h*HD+e]
// A: [M, Dm], W: [Hn, Dm, HDm], C: [B,H,T,HD] contiguous.
// Same tiling as sgemm_bias; B-tile gather respects the per-head layout.
// ---------------------------------------------------------------------------
__global__ __launch_bounds__(256, 2)
void qkv_gemm(const float* __restrict__ A, const float* __restrict__ W,
              const float* __restrict__ bias, float* __restrict__ C)
{
    __shared__ float As[8][128];
    __shared__ float Bs[8][128];

    const int tid = threadIdx.x;
    const int m0 = blockIdx.y * 128;
    const int n0 = blockIdx.x * 128;

    const int aRow = tid >> 1;
    const int aCol = (tid & 1) << 2;
    const int bRow = tid >> 5;
    const int bCol = (tid & 31) << 2;
    const int tx = tid & 15, ty = tid >> 4;

    float acc[8][8];
#pragma unroll
    for (int i = 0; i < 8; i++)
#pragma unroll
        for (int j = 0; j < 8; j++) acc[i][j] = 0.f;

    const float* Aptr = A + (size_t)(m0 + aRow) * Dm + aCol;
    // W element (k, n) at W[head*Dm*HD + k*HD + col], head=n>>6, col=n&63
    const int nB = n0 + bCol;
    const float* Wptr = W + ((size_t)(nB >> 6) * Dm) * HDm + (nB & 63);

    for (int k0 = 0; k0 < Dm; k0 += 8) {
        float4 av = *(const float4*)(Aptr + k0);
        As[aCol + 0][aRow] = av.x;
        As[aCol + 1][aRow] = av.y;
        As[aCol + 2][aRow] = av.z;
        As[aCol + 3][aRow] = av.w;
        *(float4*)&Bs[bRow][bCol] =
            *(const float4*)(Wptr + (size_t)(k0 + bRow) * HDm);
        __syncthreads();

#pragma unroll
        for (int kk = 0; kk < 8; kk++) {
            float a[8], b[8];
            *(float4*)(a)     = *(const float4*)&As[kk][ty * 4];
            *(float4*)(a + 4) = *(const float4*)&As[kk][64 + ty * 4];
            *(float4*)(b)     = *(const float4*)&Bs[kk][tx * 4];
            *(float4*)(b + 4) = *(const float4*)&Bs[kk][64 + tx * 4];
#pragma unroll
            for (int i = 0; i < 8; i++)
#pragma unroll
                for (int j = 0; j < 8; j++)
                    acc[i][j] = fmaf(a[i], b[j], acc[i][j]);
        }
        __syncthreads();
    }

    float bsv[8];
    *(float4*)(bsv)     = *(const float4*)&bias[n0 + tx * 4];
    *(float4*)(bsv + 4) = *(const float4*)&bias[n0 + 64 + tx * 4];

#pragma unroll
    for (int g = 0; g < 2; g++) {
        const int n = n0 + g * 64 + tx * 4;
        const int head = n >> 6, e = n & 63;
#pragma unroll
        for (int i = 0; i < 8; i++) {
            const int m = m0 + ((i < 4) ? (ty * 4 + i) : (60 + ty * 4 + i));
            const int b = m >> 9, t = m & 511;
            float4 v;
            v.x = acc[i][g * 4 + 0] + bsv[g * 4 + 0];
            v.y = acc[i][g * 4 + 1] + bsv[g * 4 + 1];
            v.z = acc[i][g * 4 + 2] + bsv[g * 4 + 2];
            v.w = acc[i][g * 4 + 3] + bsv[g * 4 + 3];
            *(float4*)&C[(((size_t)(b * Hn + head)) * Tlen + t) * HDm + e] = v;
        }
    }
}

// ---------------------------------------------------------------------------
// Flash-style attention with the reference's orientation:
//   S[t,s] = K[t]·Q[s], mask s<=t, softmax over s, O[t] = sum_s P[t,s] V[s].
// One block per (64 t-rows, b*h). Online softmax over s-tiles of 64.
// Output layout [B,T,H,HD] so the final GEMM reads it as [M, D].
// ---------------------------------------------------------------------------
__global__ __launch_bounds__(256)
void attn_kernel(const float* __restrict__ Kv, const float* __restrict__ Qv,
                 const float* __restrict__ Vv, float* __restrict__ O)
{
    constexpr int P = 68;  // padded row stride (conflict avoidance, 16B-aligned)
    extern __shared__ float sm[];
    float* Kt   = sm;                 // [64][P], e-major: Kt[e*P + t]
    float* Qt   = Kt + 64 * P;        // [64][P], e-major: Qt[e*P + s]
    float* Ssm  = Qt + 64 * P;        // [64][P], S[t*P + s] then P
    float* Vs   = Ssm + 64 * P;       // [64][64], Vs[s*64 + e]
    float* mrow = Vs + 64 * 64;       // [64]
    float* lrow = mrow + 64;          // [64]
    float* arow = lrow + 64;          // [64]
    float* red  = arow + 64;          // [64][4]

    const int tid = threadIdx.x;
    const int tx = tid & 15, ty = tid >> 4;
    const int t0 = blockIdx.x * 64;
    const int bh = blockIdx.y;
    const size_t base = (size_t)bh * Tlen * HDm;

    // Load K tile (64 t-rows), transposed to e-major.
    {
        const int lt = tid >> 2;
        const int le = (tid & 3) << 4;
        const float* kp = Kv + base + (size_t)(t0 + lt) * HDm + le;
#pragma unroll
        for (int i = 0; i < 16; i += 4) {
            float4 v = *(const float4*)(kp + i);
            Kt[(le + i + 0) * P + lt] = v.x;
            Kt[(le + i + 1) * P + lt] = v.y;
            Kt[(le + i + 2) * P + lt] = v.z;
            Kt[(le + i + 3) * P + lt] = v.w;
        }
    }
    if (tid < 64) { mrow[tid] = -1e30f; lrow[tid] = 0.f; }

    float o[4][4] = {};
    const int rr = tid >> 2;   // reduction row 0..63
    const int qq = tid & 3;    // reduction quarter

    for (int s0 = 0; s0 <= t0; s0 += 64) {
        // Load Q (transposed) and V tiles for this s-block.
        {
            const int lt = tid >> 2;
            const int le = (tid & 3) << 4;
            const float* qp = Qv + base + (size_t)(s0 + lt) * HDm + le;
            const float* vp = Vv + base + (size_t)(s0 + lt) * HDm + le;
#pragma unroll
            for (int i = 0; i < 16; i += 4) {
                float4 v = *(const float4*)(qp + i);
                Qt[(le + i + 0) * P + lt] = v.x;
                Qt[(le + i + 1) * P + lt] = v.y;
                Qt[(le + i + 2) * P + lt] = v.z;
                Qt[(le + i + 3) * P + lt] = v.w;
                *(float4*)&Vs[lt * 64 + le + i] = *(const float4*)(vp + i);
            }
        }
        __syncthreads();

        // S = K @ Q^T (4x4 per thread)
        float sacc[4][4] = {};
#pragma unroll 8
        for (int e = 0; e < 64; e++) {
            float a[4], b[4];
            *(float4*)a = *(const float4*)&Kt[e * P + ty * 4];
            *(float4*)b = *(const float4*)&Qt[e * P + tx * 4];
#pragma unroll
            for (int i = 0; i < 4; i++)
#pragma unroll
                for (int j = 0; j < 4; j++)
                    sacc[i][j] = fmaf(a[i], b[j], sacc[i][j]);
        }
        if (s0 == t0) {  // diagonal block: valid iff s <= t
#pragma unroll
            for (int i = 0; i < 4; i++)
#pragma unroll
                for (int j = 0; j < 4; j++)
                    if (tx * 4 + j > ty * 4 + i) sacc[i][j] = -1e30f;
        }
#pragma unroll
        for (int i = 0; i < 4; i++)
            *(float4*)&Ssm[(ty * 4 + i) * P + tx * 4] = *(float4*)sacc[i];
        __syncthreads();

        // Row max (4 partials per row)
        {
            float pm = -1e30f;
            const float* srow = &Ssm[rr * P + qq * 16];
#pragma unroll
            for (int s = 0; s < 16; s++) pm = fmaxf(pm, srow[s]);
            red[rr * 4 + qq] = pm;
        }
        __syncthreads();
        if (qq == 0) {
            float mn = fmaxf(fmaxf(red[rr * 4], red[rr * 4 + 1]),
                             fmaxf(red[rr * 4 + 2], red[rr * 4 + 3]));
            mn = fmaxf(mn, mrow[rr]);
            arow[rr] = __expf(mrow[rr] - mn);
            mrow[rr] = mn;
        }
        __syncthreads();

        // exp pass + row-sum partials
        {
            const float mv = mrow[rr];
            float* srow = &Ssm[rr * P + qq * 16];
            float psum = 0.f;
#pragma unroll
            for (int s = 0; s < 16; s++) {
                float p = __expf(srow[s] - mv);
                srow[s] = p;
                psum += p;
            }
            red[rr * 4 + qq] = psum;
        }
        __syncthreads();
        if (qq == 0)
            lrow[rr] = lrow[rr] * arow[rr] +
                       (red[rr * 4] + red[rr * 4 + 1] + red[rr * 4 + 2] + red[rr * 4 + 3]);

        // Rescale O, accumulate P @ V
        float al[4];
#pragma unroll
        for (int i = 0; i < 4; i++) al[i] = arow[ty * 4 + i];
#pragma unroll
        for (int i = 0; i < 4; i++)
#pragma unroll
            for (int j = 0; j < 4; j++) o[i][j] *= al[i];

#pragma unroll 8
        for (int s = 0; s < 64; s++) {
            float b[4];
            *(float4*)b = *(const float4*)&Vs[s * 64 + tx * 4];
#pragma unroll
            for (int i = 0; i < 4; i++) {
                const float p = Ssm[(ty * 4 + i) * P + s];
#pragma unroll
                for (int j = 0; j < 4; j++)
                    o[i][j] = fmaf(p, b[j], o[i][j]);
            }
        }
        __syncthreads();
    }

    // Epilogue: normalize and write [B,T,H,HD]
    const int b = bh >> 4, h = bh & 15;
#pragma unroll
    for (int i = 0; i < 4; i++) {
        const int t = t0 + ty * 4 + i;
        const float inv = 1.f / lrow[ty * 4 + i];
        float4 v;
        v.x = o[i][0] * inv; v.y = o[i][1] * inv;
        v.z = o[i][2] * inv; v.w = o[i][3] * inv;
        *(float4*)&O[(((size_t)b * Tlen + t) * Hn + h) * HDm + tx * 4] = v;
    }
}

// ---------------------------------------------------------------------------
extern "C" void kernel_launch(void* const* d_in, const int* in_sizes, int n_in,
                              void* d_out, int out_size)
{
    const float* x  = (const float*)d_in[0];
    const float* Wi = (const float*)d_in[1];
    const float* bi = (const float*)d_in[2];
    const float* Wk = (const float*)d_in[3];
    const float* bk = (const float*)d_in[4];
    const float* Wq = (const float*)d_in[5];
    const float* bq = (const float*)d_in[6];
    const float* Wv = (const float*)d_in[7];
    const float* bv = (const float*)d_in[8];
    const float* Wo = (const float*)d_in[9];
    const float* bo = (const float*)d_in[10];
    float* out = (float*)d_out;

    float *ph, *pk, *pq, *pv, *pa;
    cudaGetSymbolAddress((void**)&ph, g_h);
    cudaGetSymbolAddress((void**)&pk, g_k);
    cudaGetSymbolAddress((void**)&pq, g_q);
    cudaGetSymbolAddress((void**)&pv, g_v);
    cudaGetSymbolAddress((void**)&pa, g_attn);

    const dim3 gGemm(Dm / 128, Mrows / 128);  // (8, 128)

    // 1) h = x @ Wi + bi
    sgemm_bias<<<gGemm, 256>>>(x, Wi, bi, ph, Mrows, Dm, Dm);

    // 2) K/Q/V projections -> [B,H,T,HD]
    qkv_gemm<<<gGemm, 256>>>(ph, Wk, bk, pk);
    qkv_gemm<<<gGemm, 256>>>(ph, Wq, bq, pq);
    qkv_gemm<<<gGemm, 256>>>(ph, Wv, bv, pv);

    // 3) attention (scores = k@q^T, causal, softmax over s) -> [B,T,H,HD]
    const int smem_bytes =
        (3 * 64 * 68 + 64 * 64 + 3 * 64 + 64 * 4) * (int)sizeof(float);  // 70400
    cudaFuncSetAttribute(attn_kernel,
                         cudaFuncAttributeMaxDynamicSharedMemorySize, smem_bytes);
    attn_kernel<<<dim3(Tlen / 64, Bsz * Hn), 256, smem_bytes>>>(pk, pq, pv, pa);

    // 4) out = attn @ Wo + bo
    sgemm_bias<<<gGemm, 256>>>(pa, Wo, bo, out, Mrows, Dm, Dm);
}

// round 7
// speedup vs baseline: 1.0008x; 1.0008x over previous
#include <cuda_runtime.h>

// Problem constants
#define Bsz   32
#define Tlen  512
#define Dm    1024
#define Hn    16
#define HDm   64
#define Mrows (Bsz * Tlen)   // 16384

// Scratch: __device__ globals (no cudaMalloc allowed). 5 x 64MB.
__device__ __align__(128) float g_h[(size_t)Mrows * Dm];
__device__ __align__(128) float g_k[(size_t)Mrows * Dm];   // [B,H,T,HD]
__device__ __align__(128) float g_q[(size_t)Mrows * Dm];   // [B,H,T,HD]
__device__ __align__(128) float g_v[(size_t)Mrows * Dm];   // [B,H,T,HD]
__device__ __align__(128) float g_attn[(size_t)Mrows * Dm]; // [B,T,H,HD] = [M,D]

// ---------------------------------------------------------------------------
// SGEMM: C[M,N] = A[M,K] @ B[K,N] + bias[N]   (all row-major, fp32)
// 128x128 block tile, BK=8, 256 threads, 8x8 per thread (2x2 of 4x4 quads).
// ---------------------------------------------------------------------------
__global__ __launch_bounds__(256, 2)
void sgemm_bias(const float* __restrict__ A, const float* __restrict__ B,
                const float* __restrict__ bias, float* __restrict__ C,
                int M, int N, int K)
{
    __shared__ float As[8][128];
    __shared__ float Bs[8][128];

    const int tid = threadIdx.x;
    const int m0 = blockIdx.y * 128;
    const int n0 = blockIdx.x * 128;

    const int aRow = tid >> 1;             // 0..127
    const int aCol = (tid & 1) << 2;       // 0 or 4
    const int bRow = tid >> 5;             // 0..7
    const int bCol = (tid & 31) << 2;      // 0..124

    const int tx = tid & 15, ty = tid >> 4;

    float acc[8][8];
#pragma unroll
    for (int i = 0; i < 8; i++)
#pragma unroll
        for (int j = 0; j < 8; j++) acc[i][j] = 0.f;

    const float* Aptr = A + (size_t)(m0 + aRow) * K + aCol;
    const float* Bptr = B + (size_t)bRow * N + n0 + bCol;

    for (int k0 = 0; k0 < K; k0 += 8) {
        float4 av = *(const float4*)(Aptr + k0);
        As[aCol + 0][aRow] = av.x;
        As[aCol + 1][aRow] = av.y;
        As[aCol + 2][aRow] = av.z;
        As[aCol + 3][aRow] = av.w;
        *(float4*)&Bs[bRow][bCol] = *(const float4*)(Bptr + (size_t)k0 * N);
        __syncthreads();

#pragma unroll
        for (int kk = 0; kk < 8; kk++) {
            float a[8], b[8];
            *(float4*)(a)     = *(const float4*)&As[kk][ty * 4];
            *(float4*)(a + 4) = *(const float4*)&As[kk][64 + ty * 4];
            *(float4*)(b)     = *(const float4*)&Bs[kk][tx * 4];
            *(float4*)(b + 4) = *(const float4*)&Bs[kk][64 + tx * 4];
#pragma unroll
            for (int i = 0; i < 8; i++)
#pragma unroll
                for (int j = 0; j < 8; j++)
                    acc[i][j] = fmaf(a[i], b[j], acc[i][j]);
        }
        __syncthreads();
    }

    float bsv[8];
    *(float4*)(bsv)     = *(const float4*)&bias[n0 + tx * 4];
    *(float4*)(bsv + 4) = *(const float4*)&bias[n0 + 64 + tx * 4];

#pragma unroll
    for (int i = 0; i < 8; i++) {
        const int m = m0 + ((i < 4) ? (ty * 4 + i) : (60 + ty * 4 + i));
        float4 v0, v1;
        v0.x = acc[i][0] + bsv[0]; v0.y = acc[i][1] + bsv[1];
        v0.z = acc[i][2] + bsv[2]; v0.w = acc[i][3] + bsv[3];
        v1.x = acc[i][4] + bsv[4]; v1.y = acc[i][5] + bsv[5];
        v1.z = acc[i][6] + bsv[6]; v1.w = acc[i][7] + bsv[7];
        *(float4*)&C[(size_t)m * N + n0 + tx * 4]      = v0;
        *(float4*)&C[(size_t)m * N + n0 + 64 + tx * 4] = v1;
    }
}

// ---------------------------------------------------------------------------
// QKV projection GEMM:
//   C[b,h,t,e] = sum_d A[(b,t),d] * W[h,d,e] + bias[h*HD+e]
// A: [M, Dm], W: [Hn, Dm, HDm], C: [B,H,T,HD] contiguous.
// Same tiling as sgemm_bias; B-tile gather respects the per-head layout.
// ---------------------------------------------------------------------------
__global__ __launch_bounds__(256, 2)
void qkv_gemm(const float* __restrict__ A, const float* __restrict__ W,
              const float* __restrict__ bias, float* __restrict__ C)
{
    __shared__ float As[8][128];
    __shared__ float Bs[8][128];

    const int tid = threadIdx.x;
    const int m0 = blockIdx.y * 128;
    const int n0 = blockIdx.x * 128;

    const int aRow = tid >> 1;
    const int aCol = (tid & 1) << 2;
    const int bRow = tid >> 5;
    const int bCol = (tid & 31) << 2;
    const int tx = tid & 15, ty = tid >> 4;

    float acc[8][8];
#pragma unroll
    for (int i = 0; i < 8; i++)
#pragma unroll
        for (int j = 0; j < 8; j++) acc[i][j] = 0.f;

    const float* Aptr = A + (size_t)(m0 + aRow) * Dm + aCol;
    // W element (k, n) at W[head*Dm*HD + k*HD + col], head=n>>6, col=n&63
    const int nB = n0 + bCol;
    const float* Wptr = W + ((size_t)(nB >> 6) * Dm) * HDm + (nB & 63);

    for (int k0 = 0; k0 < Dm; k0 += 8) {
        float4 av = *(const float4*)(Aptr + k0);
        As[aCol + 0][aRow] = av.x;
        As[aCol + 1][aRow] = av.y;
        As[aCol + 2][aRow] = av.z;
        As[aCol + 3][aRow] = av.w;
        *(float4*)&Bs[bRow][bCol] =
            *(const float4*)(Wptr + (size_t)(k0 + bRow) * HDm);
        __syncthreads();

#pragma unroll
        for (int kk = 0; kk < 8; kk++) {
            float a[8], b[8];
            *(float4*)(a)     = *(const float4*)&As[kk][ty * 4];
            *(float4*)(a + 4) = *(const float4*)&As[kk][64 + ty * 4];
            *(float4*)(b)     = *(const float4*)&Bs[kk][tx * 4];
            *(float4*)(b + 4) = *(const float4*)&Bs[kk][64 + tx * 4];
#pragma unroll
            for (int i = 0; i < 8; i++)
#pragma unroll
                for (int j = 0; j < 8; j++)
                    acc[i][j] = fmaf(a[i], b[j], acc[i][j]);
        }
        __syncthreads();
    }

    float bsv[8];
    *(float4*)(bsv)     = *(const float4*)&bias[n0 + tx * 4];
    *(float4*)(bsv + 4) = *(const float4*)&bias[n0 + 64 + tx * 4];

#pragma unroll
    for (int g = 0; g < 2; g++) {
        const int n = n0 + g * 64 + tx * 4;
        const int head = n >> 6, e = n & 63;
#pragma unroll
        for (int i = 0; i < 8; i++) {
            const int m = m0 + ((i < 4) ? (ty * 4 + i) : (60 + ty * 4 + i));
            const int b = m >> 9, t = m & 511;
            float4 v;
            v.x = acc[i][g * 4 + 0] + bsv[g * 4 + 0];
            v.y = acc[i][g * 4 + 1] + bsv[g * 4 + 1];
            v.z = acc[i][g * 4 + 2] + bsv[g * 4 + 2];
            v.w = acc[i][g * 4 + 3] + bsv[g * 4 + 3];
            *(float4*)&C[(((size_t)(b * Hn + head)) * Tlen + t) * HDm + e] = v;
        }
    }
}

// ---------------------------------------------------------------------------
// Flash-style attention with the reference's orientation:
//   S[t,s] = K[t]·Q[s], mask s<=t, softmax over s, O[t] = sum_s P[t,s] V[s].
// One block per (64 t-rows, b*h). Online softmax over s-tiles of 64.
// Output layout [B,T,H,HD] so the final GEMM reads it as [M, D].
// ---------------------------------------------------------------------------
__global__ __launch_bounds__(256)
void attn_kernel(const float* __restrict__ Kv, const float* __restrict__ Qv,
                 const float* __restrict__ Vv, float* __restrict__ O)
{
    constexpr int P = 68;  // padded row stride (conflict avoidance, 16B-aligned)
    extern __shared__ float sm[];
    float* Kt   = sm;                 // [64][P], e-major: Kt[e*P + t]
    float* Qt   = Kt + 64 * P;        // [64][P], e-major: Qt[e*P + s]
    float* Ssm  = Qt + 64 * P;        // [64][P], S[t*P + s] then P
    float* Vs   = Ssm + 64 * P;       // [64][64], Vs[s*64 + e]
    float* mrow = Vs + 64 * 64;       // [64]
    float* lrow = mrow + 64;          // [64]
    float* arow = lrow + 64;          // [64]
    float* red  = arow + 64;          // [64][4]

    const int tid = threadIdx.x;
    const int tx = tid & 15, ty = tid >> 4;
    const int t0 = blockIdx.x * 64;
    const int bh = blockIdx.y;
    const size_t base = (size_t)bh * Tlen * HDm;

    // Load K tile (64 t-rows), transposed to e-major.
    {
        const int lt = tid >> 2;
        const int le = (tid & 3) << 4;
        const float* kp = Kv + base + (size_t)(t0 + lt) * HDm + le;
#pragma unroll
        for (int i = 0; i < 16; i += 4) {
            float4 v = *(const float4*)(kp + i);
            Kt[(le + i + 0) * P + lt] = v.x;
            Kt[(le + i + 1) * P + lt] = v.y;
            Kt[(le + i + 2) * P + lt] = v.z;
            Kt[(le + i + 3) * P + lt] = v.w;
        }
    }
    if (tid < 64) { mrow[tid] = -1e30f; lrow[tid] = 0.f; }

    float o[4][4] = {};
    const int rr = tid >> 2;   // reduction row 0..63
    const int qq = tid & 3;    // reduction quarter

    for (int s0 = 0; s0 <= t0; s0 += 64) {
        // Load Q (transposed) and V tiles for this s-block.
        {
            const int lt = tid >> 2;
            const int le = (tid & 3) << 4;
            const float* qp = Qv + base + (size_t)(s0 + lt) * HDm + le;
            const float* vp = Vv + base + (size_t)(s0 + lt) * HDm + le;
#pragma unroll
            for (int i = 0; i < 16; i += 4) {
                float4 v = *(const float4*)(qp + i);
                Qt[(le + i + 0) * P + lt] = v.x;
                Qt[(le + i + 1) * P + lt] = v.y;
                Qt[(le + i + 2) * P + lt] = v.z;
                Qt[(le + i + 3) * P + lt] = v.w;
                *(float4*)&Vs[lt * 64 + le + i] = *(const float4*)(vp + i);
            }
        }
        __syncthreads();

        // S = K @ Q^T (4x4 per thread)
        float sacc[4][4] = {};
#pragma unroll 8
        for (int e = 0; e < 64; e++) {
            float a[4], b[4];
            *(float4*)a = *(const float4*)&Kt[e * P + ty * 4];
            *(float4*)b = *(const float4*)&Qt[e * P + tx * 4];
#pragma unroll
            for (int i = 0; i < 4; i++)
#pragma unroll
                for (int j = 0; j < 4; j++)
                    sacc[i][j] = fmaf(a[i], b[j], sacc[i][j]);
        }
        if (s0 == t0) {  // diagonal block: valid iff s <= t
#pragma unroll
            for (int i = 0; i < 4; i++)
#pragma unroll
                for (int j = 0; j < 4; j++)
                    if (tx * 4 + j > ty * 4 + i) sacc[i][j] = -1e30f;
        }
#pragma unroll
        for (int i = 0; i < 4; i++)
            *(float4*)&Ssm[(ty * 4 + i) * P + tx * 4] = *(float4*)sacc[i];
        __syncthreads();

        // Row max (4 partials per row)
        {
            float pm = -1e30f;
            const float* srow = &Ssm[rr * P + qq * 16];
#pragma unroll
            for (int s = 0; s < 16; s++) pm = fmaxf(pm, srow[s]);
            red[rr * 4 + qq] = pm;
        }
        __syncthreads();
        if (qq == 0) {
            float mn = fmaxf(fmaxf(red[rr * 4], red[rr * 4 + 1]),
                             fmaxf(red[rr * 4 + 2], red[rr * 4 + 3]));
            mn = fmaxf(mn, mrow[rr]);
            arow[rr] = __expf(mrow[rr] - mn);
            mrow[rr] = mn;
        }
        __syncthreads();

        // exp pass + row-sum partials
        {
            const float mv = mrow[rr];
            float* srow = &Ssm[rr * P + qq * 16];
            float psum = 0.f;
#pragma unroll
            for (int s = 0; s < 16; s++) {
                float p = __expf(srow[s] - mv);
                srow[s] = p;
                psum += p;
            }
            red[rr * 4 + qq] = psum;
        }
        __syncthreads();
        if (qq == 0)
            lrow[rr] = lrow[rr] * arow[rr] +
                       (red[rr * 4] + red[rr * 4 + 1] + red[rr * 4 + 2] + red[rr * 4 + 3]);

        // Rescale O, accumulate P @ V
        float al[4];
#pragma unroll
        for (int i = 0; i < 4; i++) al[i] = arow[ty * 4 + i];
#pragma unroll
        for (int i = 0; i < 4; i++)
#pragma unroll
            for (int j = 0; j < 4; j++) o[i][j] *= al[i];

#pragma unroll 8
        for (int s = 0; s < 64; s++) {
            float b[4];
            *(float4*)b = *(const float4*)&Vs[s * 64 + tx * 4];
#pragma unroll
            for (int i = 0; i < 4; i++) {
                const float p = Ssm[(ty * 4 + i) * P + s];
#pragma unroll
                for (int j = 0; j < 4; j++)
                    o[i][j] = fmaf(p, b[j], o[i][j]);
            }
        }
        __syncthreads();
    }

    // Epilogue: normalize and write [B,T,H,HD]
    const int b = bh >> 4, h = bh & 15;
#pragma unroll
    for (int i = 0; i < 4; i++) {
        const int t = t0 + ty * 4 + i;
        const float inv = 1.f / lrow[ty * 4 + i];
        float4 v;
        v.x = o[i][0] * inv; v.y = o[i][1] * inv;
        v.z = o[i][2] * inv; v.w = o[i][3] * inv;
        *(float4*)&O[(((size_t)b * Tlen + t) * Hn + h) * HDm + tx * 4] = v;
    }
}

// ---------------------------------------------------------------------------
extern "C" void kernel_launch(void* const* d_in, const int* in_sizes, int n_in,
                              void* d_out, int out_size)
{
    const float* x  = (const float*)d_in[0];
    const float* Wi = (const float*)d_in[1];
    const float* bi = (const float*)d_in[2];
    const float* Wk = (const float*)d_in[3];
    const float* bk = (const float*)d_in[4];
    const float* Wq = (const float*)d_in[5];
    const float* bq = (const float*)d_in[6];
    const float* Wv = (const float*)d_in[7];
    const float* bv = (const float*)d_in[8];
    const float* Wo = (const float*)d_in[9];
    const float* bo = (const float*)d_in[10];
    float* out = (float*)d_out;

    float *ph, *pk, *pq, *pv, *pa;
    cudaGetSymbolAddress((void**)&ph, g_h);
    cudaGetSymbolAddress((void**)&pk, g_k);
    cudaGetSymbolAddress((void**)&pq, g_q);
    cudaGetSymbolAddress((void**)&pv, g_v);
    cudaGetSymbolAddress((void**)&pa, g_attn);

    const dim3 gGemm(Dm / 128, Mrows / 128);  // (8, 128)

    // 1) h = x @ Wi + bi
    sgemm_bias<<<gGemm, 256>>>(x, Wi, bi, ph, Mrows, Dm, Dm);

    // 2) K/Q/V projections -> [B,H,T,HD]
    qkv_gemm<<<gGemm, 256>>>(ph, Wk, bk, pk);
    qkv_gemm<<<gGemm, 256>>>(ph, Wq, bq, pq);
    qkv_gemm<<<gGemm, 256>>>(ph, Wv, bv, pv);

    // 3) attention (scores = k@q^T, causal, softmax over s) -> [B,T,H,HD]
    const int smem_bytes =
        (3 * 64 * 68 + 64 * 64 + 3 * 64 + 64 * 4) * (int)sizeof(float);  // 70400
    cudaFuncSetAttribute(attn_kernel,
                         cudaFuncAttributeMaxDynamicSharedMemorySize, smem_bytes);
    attn_kernel<<<dim3(Tlen / 64, Bsz * Hn), 256, smem_bytes>>>(pk, pq, pv, pa);

    // 4) out = attn @ Wo + bo
    sgemm_bias<<<gGemm, 256>>>(pa, Wo, bo, out, Mrows, Dm, Dm);
}

// round 8
// speedup vs baseline: 1.0021x; 1.0013x over previous
#include <cuda_runtime.h>

// Problem constants
#define Bsz   32
#define Tlen  512
#define Dm    1024
#define Hn    16
#define HDm   64
#define Mrows (Bsz * Tlen)   // 16384

// Scratch: __device__ globals (no cudaMalloc allowed). 5 x 64MB.
__device__ __align__(128) float g_h[(size_t)Mrows * Dm];
__device__ __align__(128) float g_k[(size_t)Mrows * Dm];   // [B,H,T,HD]
__device__ __align__(128) float g_q[(size_t)Mrows * Dm];   // [B,H,T,HD]
__device__ __align__(128) float g_v[(size_t)Mrows * Dm];   // [B,H,T,HD]
__device__ __align__(128) float g_attn[(size_t)Mrows * Dm]; // [B,T,H,HD] = [M,D]

// ---------------------------------------------------------------------------
// SGEMM: C[M,N] = A[M,K] @ B[K,N] + bias[N]   (all row-major, fp32)
// 128x128 block tile, BK=8, 256 threads, 8x8 per thread (2x2 of 4x4 quads).
// ---------------------------------------------------------------------------
__global__ __launch_bounds__(256, 2)
void sgemm_bias(const float* __restrict__ A, const float* __restrict__ B,
                const float* __restrict__ bias, float* __restrict__ C,
                int M, int N, int K)
{
    __shared__ float As[8][128];
    __shared__ float Bs[8][128];

    const int tid = threadIdx.x;
    const int m0 = blockIdx.y * 128;
    const int n0 = blockIdx.x * 128;

    const int aRow = tid >> 1;             // 0..127
    const int aCol = (tid & 1) << 2;       // 0 or 4
    const int bRow = tid >> 5;             // 0..7
    const int bCol = (tid & 31) << 2;      // 0..124

    const int tx = tid & 15, ty = tid >> 4;

    float acc[8][8];
#pragma unroll
    for (int i = 0; i < 8; i++)
#pragma unroll
        for (int j = 0; j < 8; j++) acc[i][j] = 0.f;

    const float* Aptr = A + (size_t)(m0 + aRow) * K + aCol;
    const float* Bptr = B + (size_t)bRow * N + n0 + bCol;

    for (int k0 = 0; k0 < K; k0 += 8) {
        float4 av = *(const float4*)(Aptr + k0);
        As[aCol + 0][aRow] = av.x;
        As[aCol + 1][aRow] = av.y;
        As[aCol + 2][aRow] = av.z;
        As[aCol + 3][aRow] = av.w;
        *(float4*)&Bs[bRow][bCol] = *(const float4*)(Bptr + (size_t)k0 * N);
        __syncthreads();

#pragma unroll
        for (int kk = 0; kk < 8; kk++) {
            float a[8], b[8];
            *(float4*)(a)     = *(const float4*)&As[kk][ty * 4];
            *(float4*)(a + 4) = *(const float4*)&As[kk][64 + ty * 4];
            *(float4*)(b)     = *(const float4*)&Bs[kk][tx * 4];
            *(float4*)(b + 4) = *(const float4*)&Bs[kk][64 + tx * 4];
#pragma unroll
            for (int i = 0; i < 8; i++)
#pragma unroll
                for (int j = 0; j < 8; j++)
                    acc[i][j] = fmaf(a[i], b[j], acc[i][j]);
        }
        __syncthreads();
    }

    float bsv[8];
    *(float4*)(bsv)     = *(const float4*)&bias[n0 + tx * 4];
    *(float4*)(bsv + 4) = *(const float4*)&bias[n0 + 64 + tx * 4];

#pragma unroll
    for (int i = 0; i < 8; i++) {
        const int m = m0 + ((i < 4) ? (ty * 4 + i) : (60 + ty * 4 + i));
        float4 v0, v1;
        v0.x = acc[i][0] + bsv[0]; v0.y = acc[i][1] + bsv[1];
        v0.z = acc[i][2] + bsv[2]; v0.w = acc[i][3] + bsv[3];
        v1.x = acc[i][4] + bsv[4]; v1.y = acc[i][5] + bsv[5];
        v1.z = acc[i][6] + bsv[6]; v1.w = acc[i][7] + bsv[7];
        *(float4*)&C[(size_t)m * N + n0 + tx * 4]      = v0;
        *(float4*)&C[(size_t)m * N + n0 + 64 + tx * 4] = v1;
    }
}

// ---------------------------------------------------------------------------
// QKV projection GEMM:
//   C[b,h,t,e] = sum_d A[(b,t),d] * W[h,d,e] + bias[h*HD+e]
// A: [M, Dm], W: [Hn, Dm, HDm], C: [B,H,T,HD] contiguous.
// Same tiling as sgemm_bias; B-tile gather respects the per-head layout.
// ---------------------------------------------------------------------------
__global__ __launch_bounds__(256, 2)
void qkv_gemm(const float* __restrict__ A, const float* __restrict__ W,
              const float* __restrict__ bias, float* __restrict__ C)
{
    __shared__ float As[8][128];
    __shared__ float Bs[8][128];

    const int tid = threadIdx.x;
    const int m0 = blockIdx.y * 128;
    const int n0 = blockIdx.x * 128;

    const int aRow = tid >> 1;
    const int aCol = (tid & 1) << 2;
    const int bRow = tid >> 5;
    const int bCol = (tid & 31) << 2;
    const int tx = tid & 15, ty = tid >> 4;

    float acc[8][8];
#pragma unroll
    for (int i = 0; i < 8; i++)
#pragma unroll
        for (int j = 0; j < 8; j++) acc[i][j] = 0.f;

    const float* Aptr = A + (size_t)(m0 + aRow) * Dm + aCol;
    // W element (k, n) at W[head*Dm*HD + k*HD + col], head=n>>6, col=n&63
    const int nB = n0 + bCol;
    const float* Wptr = W + ((size_t)(nB >> 6) * Dm) * HDm + (nB & 63);

    for (int k0 = 0; k0 < Dm; k0 += 8) {
        float4 av = *(const float4*)(Aptr + k0);
        As[aCol + 0][aRow] = av.x;
        As[aCol + 1][aRow] = av.y;
        As[aCol + 2][aRow] = av.z;
        As[aCol + 3][aRow] = av.w;
        *(float4*)&Bs[bRow][bCol] =
            *(const float4*)(Wptr + (size_t)(k0 + bRow) * HDm);
        __syncthreads();

#pragma unroll
        for (int kk = 0; kk < 8; kk++) {
            float a[8], b[8];
            *(float4*)(a)     = *(const float4*)&As[kk][ty * 4];
            *(float4*)(a + 4) = *(const float4*)&As[kk][64 + ty * 4];
            *(float4*)(b)     = *(const float4*)&Bs[kk][tx * 4];
            *(float4*)(b + 4) = *(const float4*)&Bs[kk][64 + tx * 4];
#pragma unroll
            for (int i = 0; i < 8; i++)
#pragma unroll
                for (int j = 0; j < 8; j++)
                    acc[i][j] = fmaf(a[i], b[j], acc[i][j]);
        }
        __syncthreads();
    }

    float bsv[8];
    *(float4*)(bsv)     = *(const float4*)&bias[n0 + tx * 4];
    *(float4*)(bsv + 4) = *(const float4*)&bias[n0 + 64 + tx * 4];

#pragma unroll
    for (int g = 0; g < 2; g++) {
        const int n = n0 + g * 64 + tx * 4;
        const int head = n >> 6, e = n & 63;
#pragma unroll
        for (int i = 0; i < 8; i++) {
            const int m = m0 + ((i < 4) ? (ty * 4 + i) : (60 + ty * 4 + i));
            const int b = m >> 9, t = m & 511;
            float4 v;
            v.x = acc[i][g * 4 + 0] + bsv[g * 4 + 0];
            v.y = acc[i][g * 4 + 1] + bsv[g * 4 + 1];
            v.z = acc[i][g * 4 + 2] + bsv[g * 4 + 2];
            v.w = acc[i][g * 4 + 3] + bsv[g * 4 + 3];
            *(float4*)&C[(((size_t)(b * Hn + head)) * Tlen + t) * HDm + e] = v;
        }
    }
}

// ---------------------------------------------------------------------------
// Flash-style attention with the reference's orientation:
//   S[t,s] = K[t]·Q[s], mask s<=t, softmax over s, O[t] = sum_s P[t,s] V[s].
// One block per (64 t-rows, b*h). Online softmax over s-tiles of 64.
// Output layout [B,T,H,HD] so the final GEMM reads it as [M, D].
// ---------------------------------------------------------------------------
__global__ __launch_bounds__(256)
void attn_kernel(const float* __restrict__ Kv, const float* __restrict__ Qv,
                 const float* __restrict__ Vv, float* __restrict__ O)
{
    constexpr int P = 68;  // padded row stride (conflict avoidance, 16B-aligned)
    extern __shared__ float sm[];
    float* Kt   = sm;                 // [64][P], e-major: Kt[e*P + t]
    float* Qt   = Kt + 64 * P;        // [64][P], e-major: Qt[e*P + s]
    float* Ssm  = Qt + 64 * P;        // [64][P], S[t*P + s] then P
    float* Vs   = Ssm + 64 * P;       // [64][64], Vs[s*64 + e]
    float* mrow = Vs + 64 * 64;       // [64]
    float* lrow = mrow + 64;          // [64]
    float* arow = lrow + 64;          // [64]
    float* red  = arow + 64;          // [64][4]

    const int tid = threadIdx.x;
    const int tx = tid & 15, ty = tid >> 4;
    const int t0 = blockIdx.x * 64;
    const int bh = blockIdx.y;
    const size_t base = (size_t)bh * Tlen * HDm;

    // Load K tile (64 t-rows), transposed to e-major.
    {
        const int lt = tid >> 2;
        const int le = (tid & 3) << 4;
        const float* kp = Kv + base + (size_t)(t0 + lt) * HDm + le;
#pragma unroll
        for (int i = 0; i < 16; i += 4) {
            float4 v = *(const float4*)(kp + i);
            Kt[(le + i + 0) * P + lt] = v.x;
            Kt[(le + i + 1) * P + lt] = v.y;
            Kt[(le + i + 2) * P + lt] = v.z;
            Kt[(le + i + 3) * P + lt] = v.w;
        }
    }
    if (tid < 64) { mrow[tid] = -1e30f; lrow[tid] = 0.f; }

    float o[4][4] = {};
    const int rr = tid >> 2;   // reduction row 0..63
    const int qq = tid & 3;    // reduction quarter

    for (int s0 = 0; s0 <= t0; s0 += 64) {
        // Load Q (transposed) and V tiles for this s-block.
        {
            const int lt = tid >> 2;
            const int le = (tid & 3) << 4;
            const float* qp = Qv + base + (size_t)(s0 + lt) * HDm + le;
            const float* vp = Vv + base + (size_t)(s0 + lt) * HDm + le;
#pragma unroll
            for (int i = 0; i < 16; i += 4) {
                float4 v = *(const float4*)(qp + i);
                Qt[(le + i + 0) * P + lt] = v.x;
                Qt[(le + i + 1) * P + lt] = v.y;
                Qt[(le + i + 2) * P + lt] = v.z;
                Qt[(le + i + 3) * P + lt] = v.w;
                *(float4*)&Vs[lt * 64 + le + i] = *(const float4*)(vp + i);
            }
        }
        __syncthreads();

        // S = K @ Q^T (4x4 per thread)
        float sacc[4][4] = {};
#pragma unroll 8
        for (int e = 0; e < 64; e++) {
            float a[4], b[4];
            *(float4*)a = *(const float4*)&Kt[e * P + ty * 4];
            *(float4*)b = *(const float4*)&Qt[e * P + tx * 4];
#pragma unroll
            for (int i = 0; i < 4; i++)
#pragma unroll
                for (int j = 0; j < 4; j++)
                    sacc[i][j] = fmaf(a[i], b[j], sacc[i][j]);
        }
        if (s0 == t0) {  // diagonal block: valid iff s <= t
#pragma unroll
            for (int i = 0; i < 4; i++)
#pragma unroll
                for (int j = 0; j < 4; j++)
                    if (tx * 4 + j > ty * 4 + i) sacc[i][j] = -1e30f;
        }
#pragma unroll
        for (int i = 0; i < 4; i++)
            *(float4*)&Ssm[(ty * 4 + i) * P + tx * 4] = *(float4*)sacc[i];
        __syncthreads();

        // Row max (4 partials per row)
        {
            float pm = -1e30f;
            const float* srow = &Ssm[rr * P + qq * 16];
#pragma unroll
            for (int s = 0; s < 16; s++) pm = fmaxf(pm, srow[s]);
            red[rr * 4 + qq] = pm;
        }
        __syncthreads();
        if (qq == 0) {
            float mn = fmaxf(fmaxf(red[rr * 4], red[rr * 4 + 1]),
                             fmaxf(red[rr * 4 + 2], red[rr * 4 + 3]));
            mn = fmaxf(mn, mrow[rr]);
            arow[rr] = __expf(mrow[rr] - mn);
            mrow[rr] = mn;
        }
        __syncthreads();

        // exp pass + row-sum partials
        {
            const float mv = mrow[rr];
            float* srow = &Ssm[rr * P + qq * 16];
            float psum = 0.f;
#pragma unroll
            for (int s = 0; s < 16; s++) {
                float p = __expf(srow[s] - mv);
                srow[s] = p;
                psum += p;
            }
            red[rr * 4 + qq] = psum;
        }
        __syncthreads();
        if (qq == 0)
            lrow[rr] = lrow[rr] * arow[rr] +
                       (red[rr * 4] + red[rr * 4 + 1] + red[rr * 4 + 2] + red[rr * 4 + 3]);

        // Rescale O, accumulate P @ V
        float al[4];
#pragma unroll
        for (int i = 0; i < 4; i++) al[i] = arow[ty * 4 + i];
#pragma unroll
        for (int i = 0; i < 4; i++)
#pragma unroll
            for (int j = 0; j < 4; j++) o[i][j] *= al[i];

#pragma unroll 8
        for (int s = 0; s < 64; s++) {
            float b[4];
            *(float4*)b = *(const float4*)&Vs[s * 64 + tx * 4];
#pragma unroll
            for (int i = 0; i < 4; i++) {
                const float p = Ssm[(ty * 4 + i) * P + s];
#pragma unroll
                for (int j = 0; j < 4; j++)
                    o[i][j] = fmaf(p, b[j], o[i][j]);
            }
        }
        __syncthreads();
    }

    // Epilogue: normalize and write [B,T,H,HD]
    const int b = bh >> 4, h = bh & 15;
#pragma unroll
    for (int i = 0; i < 4; i++) {
        const int t = t0 + ty * 4 + i;
        const float inv = 1.f / lrow[ty * 4 + i];
        float4 v;
        v.x = o[i][0] * inv; v.y = o[i][1] * inv;
        v.z = o[i][2] * inv; v.w = o[i][3] * inv;
        *(float4*)&O[(((size_t)b * Tlen + t) * Hn + h) * HDm + tx * 4] = v;
    }
}

// ---------------------------------------------------------------------------
extern "C" void kernel_launch(void* const* d_in, const int* in_sizes, int n_in,
                              void* d_out, int out_size)
{
    const float* x  = (const float*)d_in[0];
    const float* Wi = (const float*)d_in[1];
    const float* bi = (const float*)d_in[2];
    const float* Wk = (const float*)d_in[3];
    const float* bk = (const float*)d_in[4];
    const float* Wq = (const float*)d_in[5];
    const float* bq = (const float*)d_in[6];
    const float* Wv = (const float*)d_in[7];
    const float* bv = (const float*)d_in[8];
    const float* Wo = (const float*)d_in[9];
    const float* bo = (const float*)d_in[10];
    float* out = (float*)d_out;

    float *ph, *pk, *pq, *pv, *pa;
    cudaGetSymbolAddress((void**)&ph, g_h);
    cudaGetSymbolAddress((void**)&pk, g_k);
    cudaGetSymbolAddress((void**)&pq, g_q);
    cudaGetSymbolAddress((void**)&pv, g_v);
    cudaGetSymbolAddress((void**)&pa, g_attn);

    const dim3 gGemm(Dm / 128, Mrows / 128);  // (8, 128)

    // 1) h = x @ Wi + bi
    sgemm_bias<<<gGemm, 256>>>(x, Wi, bi, ph, Mrows, Dm, Dm);

    // 2) K/Q/V projections -> [B,H,T,HD]
    qkv_gemm<<<gGemm, 256>>>(ph, Wk, bk, pk);
    qkv_gemm<<<gGemm, 256>>>(ph, Wq, bq, pq);
    qkv_gemm<<<gGemm, 256>>>(ph, Wv, bv, pv);

    // 3) attention (scores = k@q^T, causal, softmax over s) -> [B,T,H,HD]
    const int smem_bytes =
        (3 * 64 * 68 + 64 * 64 + 3 * 64 + 64 * 4) * (int)sizeof(float);  // 70400
    cudaFuncSetAttribute(attn_kernel,
                         cudaFuncAttributeMaxDynamicSharedMemorySize, smem_bytes);
    attn_kernel<<<dim3(Tlen / 64, Bsz * Hn), 256, smem_bytes>>>(pk, pq, pv, pa);

    // 4) out = attn @ Wo + bo
    sgemm_bias<<<gGemm, 256>>>(pa, Wo, bo, out, Mrows, Dm, Dm);
}